// round 1
// baseline (speedup 1.0000x reference)
#include <cuda_runtime.h>

// Problem constants (fixed by reference: B=1, T=8, C=64, H=W=32, F=10)
#define N_TOK 8192
#define NF 10
#define C_DIM 64
#define M_CHUNKS 16
#define M_CHUNK (N_TOK / M_CHUNKS)   // 512
#define TILE_M 128                   // m's per shared-memory stage (10 KB)
#define BLOCK_ROWS 128               // threads per attn block, 1 row each

// Scratch (static __device__ arrays — no allocation at runtime)
__device__ float  g_q[N_TOK * NF];                    // q[n][f]
__device__ float4 g_kv4[N_TOK * 5];                   // per token: k[0..9], v[0..9] (80B)
__device__ float  g_part[M_CHUNKS * N_TOK * NF];      // partial outputs per m-chunk

// ---------------- packed f32x2 helpers ----------------
__device__ __forceinline__ unsigned long long pack2f(float lo, float hi) {
    unsigned long long r;
    asm("mov.b64 %0, {%1, %2};" : "=l"(r) : "f"(lo), "f"(hi));
    return r;
}
__device__ __forceinline__ void unpack2f(unsigned long long p, float& lo, float& hi) {
    asm("mov.b64 {%0, %1}, %2;" : "=f"(lo), "=f"(hi) : "l"(p));
}
__device__ __forceinline__ unsigned long long fma2(unsigned long long a,
                                                   unsigned long long b,
                                                   unsigned long long c) {
    unsigned long long d;
    asm("fma.rn.f32x2 %0, %1, %2, %3;" : "=l"(d) : "l"(a), "l"(b), "l"(c));
    return d;
}
__device__ __forceinline__ unsigned long long mul2(unsigned long long a,
                                                   unsigned long long b) {
    unsigned long long d;
    asm("mul.rn.f32x2 %0, %1, %2;" : "=l"(d) : "l"(a), "l"(b));
    return d;
}

// ---------------- Kernel 1: projections q, k, v ----------------
// q[n,f] = sum_c w1[f,c]*x1[c,n] + b1[f]   (x1[c,n] = in1[t, c, hw], n = t*1024 + hw)
// k[n,f] = sum_c w2[f,c]*x2[c,n] + b2[f]
// v[n,f] = sum_c w3[f,c]*x1[c,n] + b3[f]
__global__ __launch_bounds__(256) void proj_kernel(
    const float* __restrict__ in1, const float* __restrict__ in2,
    const float* __restrict__ w1, const float* __restrict__ b1,
    const float* __restrict__ w2, const float* __restrict__ b2,
    const float* __restrict__ w3, const float* __restrict__ b3)
{
    __shared__ float ws1[NF * C_DIM], ws2[NF * C_DIM], ws3[NF * C_DIM];
    const int tid = threadIdx.x;
    for (int i = tid; i < NF * C_DIM; i += blockDim.x) {
        ws1[i] = w1[i]; ws2[i] = w2[i]; ws3[i] = w3[i];
    }
    __syncthreads();

    const int n  = blockIdx.x * blockDim.x + tid;
    const int t  = n >> 10;
    const int hw = n & 1023;
    const float* x1 = in1 + t * (C_DIM * 1024) + hw;
    const float* x2 = in2 + t * (C_DIM * 1024) + hw;

    float qa[NF], ka[NF], va[NF];
#pragma unroll
    for (int f = 0; f < NF; f++) { qa[f] = 0.f; ka[f] = 0.f; va[f] = 0.f; }

#pragma unroll 4
    for (int c = 0; c < C_DIM; c++) {
        float a  = x1[c << 10];
        float bb = x2[c << 10];
#pragma unroll
        for (int f = 0; f < NF; f++) {
            qa[f] = fmaf(ws1[f * C_DIM + c], a,  qa[f]);
            ka[f] = fmaf(ws2[f * C_DIM + c], bb, ka[f]);
            va[f] = fmaf(ws3[f * C_DIM + c], a,  va[f]);
        }
    }
#pragma unroll
    for (int f = 0; f < NF; f++) {
        qa[f] += __ldg(b1 + f);
        ka[f] += __ldg(b2 + f);
        va[f] += __ldg(b3 + f);
        g_q[n * NF + f] = qa[f];
    }
    float4* kv = g_kv4 + n * 5;
    kv[0] = make_float4(ka[0], ka[1], ka[2], ka[3]);
    kv[1] = make_float4(ka[4], ka[5], ka[6], ka[7]);
    kv[2] = make_float4(ka[8], ka[9], va[0], va[1]);
    kv[3] = make_float4(va[2], va[3], va[4], va[5]);
    kv[4] = make_float4(va[6], va[7], va[8], va[9]);
}

// ---------------- Kernel 2: fused relu-attention over an m-chunk ----------------
// Each thread owns one n row; block loops over its chunk's m in shared-memory tiles.
// part[chunk][n][f] = sum_{m in chunk} relu(q[n]·k[m]) * v[m][f]
__global__ __launch_bounds__(BLOCK_ROWS) void attn_kernel()
{
    __shared__ ulonglong2 skv[TILE_M * 5];   // per m: 5 x 16B = k[10], v[10]

    const int tid   = threadIdx.x;
    const int n     = blockIdx.x * BLOCK_ROWS + tid;
    const int chunk = blockIdx.y;

    unsigned long long q2[5], acc[5];
    const float* qr = g_q + n * NF;
#pragma unroll
    for (int j = 0; j < 5; j++) {
        q2[j]  = pack2f(qr[2 * j], qr[2 * j + 1]);
        acc[j] = 0ull;  // {+0.f, +0.f}
    }

    const ulonglong2* gkv =
        reinterpret_cast<const ulonglong2*>(g_kv4) + (size_t)chunk * M_CHUNK * 5;

    for (int stage = 0; stage < M_CHUNK / TILE_M; ++stage) {
        __syncthreads();
#pragma unroll
        for (int i = tid; i < TILE_M * 5; i += BLOCK_ROWS)
            skv[i] = gkv[stage * (TILE_M * 5) + i];
        __syncthreads();

#pragma unroll 4
        for (int m = 0; m < TILE_M; ++m) {
            const ulonglong2* p = skv + m * 5;
            ulonglong2 t0 = p[0], t1 = p[1], t2 = p[2], t3 = p[3], t4 = p[4];
            // s2 = sum over f-pairs of q2 ⊙ k2  (packed, 1 mul2 + 4 fma2)
            unsigned long long s2 = mul2(q2[0], t0.x);
            s2 = fma2(q2[1], t0.y, s2);
            s2 = fma2(q2[2], t1.x, s2);
            s2 = fma2(q2[3], t1.y, s2);
            s2 = fma2(q2[4], t2.x, s2);
            float slo, shi;
            unpack2f(s2, slo, shi);
            float s = fmaxf(slo + shi, 0.0f);       // relu(q·k)
            unsigned long long ss = pack2f(s, s);
            // acc[f-pair] += s * v[f-pair]  (5 fma2)
            acc[0] = fma2(ss, t2.y, acc[0]);
            acc[1] = fma2(ss, t3.x, acc[1]);
            acc[2] = fma2(ss, t3.y, acc[2]);
            acc[3] = fma2(ss, t4.x, acc[3]);
            acc[4] = fma2(ss, t4.y, acc[4]);
        }
    }

    float* out = g_part + (size_t)chunk * (N_TOK * NF) + n * NF;
#pragma unroll
    for (int j = 0; j < 5; j++) {
        float lo, hi;
        unpack2f(acc[j], lo, hi);
        out[2 * j]     = lo;
        out[2 * j + 1] = hi;
    }
}

// ---------------- Kernel 3: deterministic fixed-order reduce + output permute ----------------
// out[t, f, h, w] = sum_chunks part[chunk][n = t*1024 + hw][f]
__global__ __launch_bounds__(256) void reduce_kernel(float* __restrict__ out)
{
    const int idx = blockIdx.x * blockDim.x + threadIdx.x;   // < 81920
    const int hw  = idx & 1023;
    const int f   = (idx >> 10) % NF;
    const int t   = idx / (NF * 1024);
    const int n   = t * 1024 + hw;
    float s = 0.f;
#pragma unroll
    for (int c = 0; c < M_CHUNKS; c++)
        s += g_part[c * (N_TOK * NF) + n * NF + f];
    out[idx] = s;
}

extern "C" void kernel_launch(void* const* d_in, const int* in_sizes, int n_in,
                              void* d_out, int out_size)
{
    const float* in1 = (const float*)d_in[0];
    const float* in2 = (const float*)d_in[1];
    const float* w1  = (const float*)d_in[2];
    const float* b1  = (const float*)d_in[3];
    const float* w2  = (const float*)d_in[4];
    const float* b2  = (const float*)d_in[5];
    const float* w3  = (const float*)d_in[6];
    const float* b3  = (const float*)d_in[7];

    proj_kernel<<<N_TOK / 256, 256>>>(in1, in2, w1, b1, w2, b2, w3, b3);

    dim3 grid(N_TOK / BLOCK_ROWS, M_CHUNKS);
    attn_kernel<<<grid, BLOCK_ROWS>>>();

    reduce_kernel<<<(N_TOK * NF) / 256, 256>>>((float*)d_out);
}

// round 2
// speedup vs baseline: 1.1740x; 1.1740x over previous
#include <cuda_runtime.h>

// Problem constants (fixed by reference: B=1, T=8, C=64, H=W=32, F=10)
#define N_TOK 8192
#define NF 10
#define C_DIM 64
#define M_CHUNKS 16
#define M_CHUNK (N_TOK / M_CHUNKS)   // 512
#define TILE_M 128                   // m's per shared-memory stage (10 KB)
#define ATTN_THREADS 128             // threads per attn block; each owns 2 rows

// Scratch (static __device__ arrays — no runtime allocation)
__device__ float  g_q[N_TOK * NF];                    // q[n][f]
__device__ float4 g_kv4[N_TOK * 5];                   // per token: k[0..9], v[0..9] (80B)
__device__ float  g_part[M_CHUNKS * N_TOK * NF];      // partial outputs per m-chunk

// ---------------- packed f32x2 helpers ----------------
__device__ __forceinline__ unsigned long long pack2f(float lo, float hi) {
    unsigned long long r;
    asm("mov.b64 %0, {%1, %2};" : "=l"(r) : "f"(lo), "f"(hi));
    return r;
}
__device__ __forceinline__ void unpack2f(unsigned long long p, float& lo, float& hi) {
    asm("mov.b64 {%0, %1}, %2;" : "=f"(lo), "=f"(hi) : "l"(p));
}
__device__ __forceinline__ unsigned long long fma2(unsigned long long a,
                                                   unsigned long long b,
                                                   unsigned long long c) {
    unsigned long long d;
    asm("fma.rn.f32x2 %0, %1, %2, %3;" : "=l"(d) : "l"(a), "l"(b), "l"(c));
    return d;
}
__device__ __forceinline__ unsigned long long mul2(unsigned long long a,
                                                   unsigned long long b) {
    unsigned long long d;
    asm("mul.rn.f32x2 %0, %1, %2;" : "=l"(d) : "l"(a), "l"(b));
    return d;
}

// ---------------- Kernel 1: projections q, k, v (4-way c-split) ----------------
// Block = 256 threads: 4 c-partitions x 64 tokens. Warps are c-partition-uniform,
// so weight LDS are broadcasts; x loads are fully coalesced across lanes.
__global__ __launch_bounds__(256) void proj_kernel(
    const float* __restrict__ in1, const float* __restrict__ in2,
    const float* __restrict__ w1, const float* __restrict__ b1,
    const float* __restrict__ w2, const float* __restrict__ b2,
    const float* __restrict__ w3, const float* __restrict__ b3)
{
    __shared__ float ws[3 * NF * C_DIM];       // w1 | w2 | w3   (7.5 KB)
    __shared__ float red[4 * 64 * 30];          // partials       (30 KB)

    const int tid = threadIdx.x;
    for (int i = tid; i < NF * C_DIM; i += 256) {
        ws[i]                   = w1[i];
        ws[NF * C_DIM + i]      = w2[i];
        ws[2 * NF * C_DIM + i]  = w3[i];
    }
    __syncthreads();

    const int part = tid >> 6;          // 0..3  (c-quarter; uniform per warp)
    const int ln   = tid & 63;          // token within block
    const int n    = blockIdx.x * 64 + ln;
    const int t    = n >> 10;
    const int hw   = n & 1023;
    const int c0   = part * 16;

    const float* x1 = in1 + t * (C_DIM * 1024) + hw;
    const float* x2 = in2 + t * (C_DIM * 1024) + hw;
    const float* ws1 = ws;
    const float* ws2 = ws + NF * C_DIM;
    const float* ws3 = ws + 2 * NF * C_DIM;

    float acc[30];
#pragma unroll
    for (int j = 0; j < 30; j++) acc[j] = 0.f;

#pragma unroll
    for (int cc = 0; cc < 16; cc++) {
        const int c = c0 + cc;
        float a  = x1[c << 10];
        float bb = x2[c << 10];
#pragma unroll
        for (int f = 0; f < NF; f++) {
            acc[f]      = fmaf(ws1[f * C_DIM + c], a,  acc[f]);
            acc[10 + f] = fmaf(ws2[f * C_DIM + c], bb, acc[10 + f]);
            acc[20 + f] = fmaf(ws3[f * C_DIM + c], a,  acc[20 + f]);
        }
    }
#pragma unroll
    for (int j = 0; j < 30; j++)
        red[part * (64 * 30) + ln * 30 + j] = acc[j];
    __syncthreads();

    // Reduce 4 partials, add bias, scatter to q / kv layouts.
    float* kvf = reinterpret_cast<float*>(g_kv4);
    for (int idx = tid; idx < 64 * 30; idx += 256) {
        const int ln2 = idx / 30;
        const int j   = idx % 30;
        const int nn  = blockIdx.x * 64 + ln2;
        float s = red[idx] + red[64 * 30 + idx] + red[2 * 64 * 30 + idx]
                + red[3 * 64 * 30 + idx];
        if (j < 10) {
            g_q[nn * NF + j] = s + __ldg(b1 + j);
        } else if (j < 20) {
            kvf[nn * 20 + (j - 10)] = s + __ldg(b2 + (j - 10));   // k
        } else {
            kvf[nn * 20 + 10 + (j - 20)] = s + __ldg(b3 + (j - 20)); // v
        }
    }
}

// ---------------- Kernel 2: fused relu-attention, 2 rows per thread ----------------
// part[chunk][n][f] = sum_{m in chunk} relu(q[n]·k[m]) * v[m][f]
__global__ __launch_bounds__(ATTN_THREADS) void attn_kernel()
{
    __shared__ ulonglong2 skv[TILE_M * 5];   // per m: k[10], v[10] = 80B

    const int tid   = threadIdx.x;
    const int chunk = blockIdx.y;
    const int n0    = blockIdx.x * (2 * ATTN_THREADS) + tid;      // row A
    const int n1    = n0 + ATTN_THREADS;                          // row B

    unsigned long long qa[5], qb[5], acca[5], accb[5];
    const unsigned long long* qpa =
        reinterpret_cast<const unsigned long long*>(g_q + n0 * NF);
    const unsigned long long* qpb =
        reinterpret_cast<const unsigned long long*>(g_q + n1 * NF);
#pragma unroll
    for (int j = 0; j < 5; j++) {
        qa[j] = qpa[j]; qb[j] = qpb[j];
        acca[j] = 0ull; accb[j] = 0ull;
    }

    const ulonglong2* gkv =
        reinterpret_cast<const ulonglong2*>(g_kv4) + (size_t)chunk * M_CHUNK * 5;

    for (int stage = 0; stage < M_CHUNK / TILE_M; ++stage) {
        __syncthreads();
#pragma unroll
        for (int i = tid; i < TILE_M * 5; i += ATTN_THREADS)
            skv[i] = gkv[stage * (TILE_M * 5) + i];
        __syncthreads();

#pragma unroll 4
        for (int m = 0; m < TILE_M; ++m) {
            const ulonglong2* p = skv + m * 5;
            ulonglong2 t0 = p[0], t1 = p[1], t2 = p[2], t3 = p[3], t4 = p[4];

            // row A dot
            unsigned long long sA = mul2(qa[0], t0.x);
            sA = fma2(qa[1], t0.y, sA);
            sA = fma2(qa[2], t1.x, sA);
            sA = fma2(qa[3], t1.y, sA);
            sA = fma2(qa[4], t2.x, sA);
            // row B dot
            unsigned long long sB = mul2(qb[0], t0.x);
            sB = fma2(qb[1], t0.y, sB);
            sB = fma2(qb[2], t1.x, sB);
            sB = fma2(qb[3], t1.y, sB);
            sB = fma2(qb[4], t2.x, sB);

            float al, ah, bl, bh;
            unpack2f(sA, al, ah);
            unpack2f(sB, bl, bh);
            float sa = fmaxf(al + ah, 0.0f);
            float sb = fmaxf(bl + bh, 0.0f);
            unsigned long long ssa = pack2f(sa, sa);
            unsigned long long ssb = pack2f(sb, sb);

            acca[0] = fma2(ssa, t2.y, acca[0]);
            acca[1] = fma2(ssa, t3.x, acca[1]);
            acca[2] = fma2(ssa, t3.y, acca[2]);
            acca[3] = fma2(ssa, t4.x, acca[3]);
            acca[4] = fma2(ssa, t4.y, acca[4]);

            accb[0] = fma2(ssb, t2.y, accb[0]);
            accb[1] = fma2(ssb, t3.x, accb[1]);
            accb[2] = fma2(ssb, t3.y, accb[2]);
            accb[3] = fma2(ssb, t4.x, accb[3]);
            accb[4] = fma2(ssb, t4.y, accb[4]);
        }
    }

    float* outA = g_part + (size_t)chunk * (N_TOK * NF) + n0 * NF;
    float* outB = g_part + (size_t)chunk * (N_TOK * NF) + n1 * NF;
#pragma unroll
    for (int j = 0; j < 5; j++) {
        float lo, hi;
        unpack2f(acca[j], lo, hi);
        outA[2 * j] = lo; outA[2 * j + 1] = hi;
        unpack2f(accb[j], lo, hi);
        outB[2 * j] = lo; outB[2 * j + 1] = hi;
    }
}

// ---------------- Kernel 3: deterministic fixed-order reduce + output permute ----------------
// out[t, f, h, w] = sum_chunks part[chunk][n = t*1024 + hw][f]
__global__ __launch_bounds__(256) void reduce_kernel(float* __restrict__ out)
{
    const int idx = blockIdx.x * blockDim.x + threadIdx.x;   // < 81920
    const int hw  = idx & 1023;
    const int f   = (idx >> 10) % NF;
    const int t   = idx / (NF * 1024);
    const int n   = t * 1024 + hw;
    float s = 0.f;
#pragma unroll
    for (int c = 0; c < M_CHUNKS; c++)
        s += g_part[c * (N_TOK * NF) + n * NF + f];
    out[idx] = s;
}

extern "C" void kernel_launch(void* const* d_in, const int* in_sizes, int n_in,
                              void* d_out, int out_size)
{
    const float* in1 = (const float*)d_in[0];
    const float* in2 = (const float*)d_in[1];
    const float* w1  = (const float*)d_in[2];
    const float* b1  = (const float*)d_in[3];
    const float* w2  = (const float*)d_in[4];
    const float* b2  = (const float*)d_in[5];
    const float* w3  = (const float*)d_in[6];
    const float* b3  = (const float*)d_in[7];

    proj_kernel<<<N_TOK / 64, 256>>>(in1, in2, w1, b1, w2, b2, w3, b3);

    dim3 grid(N_TOK / (2 * ATTN_THREADS), M_CHUNKS);
    attn_kernel<<<grid, ATTN_THREADS>>>();

    reduce_kernel<<<(N_TOK * NF) / 256, 256>>>((float*)d_out);
}